// round 2
// baseline (speedup 1.0000x reference)
#include <cuda_runtime.h>
#include <cuda_bf16.h>

// Problem constants (fixed by the dataset's reference_code)
#define HW_DIM     512
#define NB         6
#define NLOOPS     4
#define NDET       4096
#define NSAMP      128
#define NBATCH     4
#define NPTS       (NDET * NSAMP)          // 524288
#define PIX        (512 * 512)             // 262144 pixels per channel
#define B_STRIDE   (2 * NB * PIX)          // per-batch elements in input (12 ch)

// Repacked refinement: [BATCH][NB][H][W] of float2 (x,y interleaved) = 50.3 MB
__device__ float2 g_packed[NBATCH * NB * PIX];

// ---------------------------------------------------------------------------
// Kernel 1: repack [B,12,H,W] f32 -> [B,6,H,W] float2. Fully coalesced.
// Each thread handles 2 pixels of one (batch,bucket) slice -> one float4 store.
// ---------------------------------------------------------------------------
__global__ void __launch_bounds__(256)
repack_kernel(const float* __restrict__ refinement)
{
    // total pixel-pairs: NBATCH*NB*PIX/2 = 3,145,728
    int t = blockIdx.x * blockDim.x + threadIdx.x;
    const int total = NBATCH * NB * (PIX / 2);
    if (t >= total) return;

    const int pair  = t % (PIX / 2);        // pixel-pair within slice
    const int slice = t / (PIX / 2);        // b*NB + k
    const int p     = pair * 2;

    const int b = slice / NB;
    const int k = slice - b * NB;

    const float* ch0 = refinement + (long)b * B_STRIDE + (long)(2 * k)     * PIX;
    const float* ch1 = refinement + (long)b * B_STRIDE + (long)(2 * k + 1) * PIX;

    const float2 a = *reinterpret_cast<const float2*>(ch0 + p); // x of p, p+1
    const float2 c = *reinterpret_cast<const float2*>(ch1 + p); // y of p, p+1

    float4 o = make_float4(a.x, c.x, a.y, c.y); // (x_p,y_p, x_{p+1},y_{p+1})
    *reinterpret_cast<float4*>(&g_packed[(long)slice * PIX + p]) = o;
}

// ---------------------------------------------------------------------------
// Kernel 2: iterative refinement gather on the packed volume.
// 2 taps (off=-1 provably zero-weight), 2 float2 gathers per iteration,
// early exit when the rounded pixel reaches a fixed point (bit-exact).
// ---------------------------------------------------------------------------
__global__ void __launch_bounds__(256)
refine_kernel(const float*  __restrict__ det_in,     // [NDET, NSAMP, 2]
              const float*  __restrict__ sampling,   // [NSAMP]
              const int*    __restrict__ bvec,       // [NDET]
              float*        __restrict__ out)        // [NDET, NSAMP, 2]
{
    int t = blockIdx.x * blockDim.x + threadIdx.x;
    if (t >= NPTS) return;

    const int s = t & (NSAMP - 1);
    const int d = t >> 7;

    // Per-sample bucket setup — reproduce reference arithmetic exactly.
    const float base  = sampling[s] * (float)NB;
    const float bif   = floorf(base);
    const int   bint  = (int)bif;

    const float d0 = fabsf(bif - base);
    const float w0 = (d0 > 1.0f) ? 0.0f : (1.0f - d0);
    const float d1 = fabsf((bif + 1.0f) - base);
    const float w1 = (d1 > 1.0f) ? 0.0f : (1.0f - d1);

    const int k0 = bint % NB;
    const int k1 = (bint + 1) % NB;

    const long bb = (long)bvec[d] * NB;
    const float2* __restrict__ p0 = g_packed + (bb + k0) * PIX;
    const float2* __restrict__ p1 = g_packed + (bb + k1) * PIX;

    float2 det = reinterpret_cast<const float2*>(det_in)[t];
    float x = det.x, y = det.y;

    int prev_pix = -1;
    #pragma unroll
    for (int l = 0; l < NLOOPS; ++l) {
        float xr = rintf(x);                 // round-half-even == jnp.round
        float yr = rintf(y);
        xr = fminf(fmaxf(xr, 0.0f), (float)(HW_DIM - 1));
        yr = fminf(fmaxf(yr, 0.0f), (float)(HW_DIM - 1));
        const int pix = (int)yr * HW_DIM + (int)xr;

        // Fixed point: same pixel => identical response => det unchanged
        // for this and every remaining iteration.
        if (pix == prev_pix) break;
        prev_pix = pix;

        const float2 g0 = __ldg(p0 + pix);
        const float2 g1 = __ldg(p1 + pix);

        x = xr + (w0 * g0.x + w1 * g1.x);
        y = yr + (w0 * g0.y + w1 * g1.y);
    }

    reinterpret_cast<float2*>(out)[t] = make_float2(x, y);
}

extern "C" void kernel_launch(void* const* d_in, const int* in_sizes, int n_in,
                              void* d_out, int out_size)
{
    // Identify inputs by element count:
    //   det_indices : 1048576 f32, refinement : 12582912 f32,
    //   sampling : 128 f32, b : 4096 i32
    const float* det_in     = nullptr;
    const float* refinement = nullptr;
    const float* sampling   = nullptr;
    const int*   bvec       = nullptr;

    for (int i = 0; i < n_in; ++i) {
        switch (in_sizes[i]) {
            case 1048576:  det_in     = (const float*)d_in[i]; break;
            case 12582912: refinement = (const float*)d_in[i]; break;
            case 128:      sampling   = (const float*)d_in[i]; break;
            case 4096:     bvec       = (const int*)d_in[i];   break;
            default: break;
        }
    }

    {
        const int total   = NBATCH * NB * (PIX / 2);
        const int threads = 256;
        const int blocks  = (total + threads - 1) / threads;
        repack_kernel<<<blocks, threads>>>(refinement);
    }
    {
        const int threads = 256;
        const int blocks  = (NPTS + threads - 1) / threads;
        refine_kernel<<<blocks, threads>>>(det_in, sampling, bvec,
                                           (float*)d_out);
    }
}